// round 6
// baseline (speedup 1.0000x reference)
#include <cuda_runtime.h>
#include <math.h>

#define B_   128
#define P_   2048
#define NB_  2000
#define NF_  250
#define NC_  16
#define R_   128
#define LS_  1750      // NB - NF
#define FT_  1751      // NB - NF + 1
#define NW_  63        // 32-bit words covering NB=2000
#define NWP_ 64        // padded row stride in words

typedef unsigned long long ull;

// ---- packed f32x2 helpers (sm_103a FFMA2 path; ptxas won't emit from C++) ----
__device__ __forceinline__ ull mul2(ull a, ull b) {
    ull d; asm("mul.rn.f32x2 %0, %1, %2;" : "=l"(d) : "l"(a), "l"(b)); return d;
}
__device__ __forceinline__ ull fma2(ull a, ull b, ull c) {
    ull d; asm("fma.rn.f32x2 %0, %1, %2, %3;" : "=l"(d) : "l"(a), "l"(b), "l"(c)); return d;
}
__device__ __forceinline__ ull add2(ull a, ull b) {
    ull d; asm("add.rn.f32x2 %0, %1, %2;" : "=l"(d) : "l"(a), "l"(b)); return d;
}
__device__ __forceinline__ ull pk(float lo, float hi) {
    ull d; asm("mov.b64 %0, {%1, %2};" : "=l"(d) : "f"(lo), "f"(hi)); return d;
}
__device__ __forceinline__ void upk(float& lo, float& hi, ull v) {
    asm("mov.b64 {%0, %1}, %2;" : "=f"(lo), "=f"(hi) : "l"(v));
}

// ---------------- scratch (static device globals; no allocations) ----------------
__device__ float d_filt[FT_];
__device__ float d_stimdot[B_];
__device__ float d_gensig[B_ * LS_];
__device__ unsigned d_bm[B_ * NC_ * NWP_];   // bitmask of cc != 0

// ---------------- K1 ----------------
__global__ void k_filt(const float* __restrict__ stim_time,
                       const float* __restrict__ stf) {
    int warp = (blockIdx.x * blockDim.x + threadIdx.x) >> 5;
    int lane = threadIdx.x & 31;
    if (warp >= FT_) return;
    double a = 0.0;
    #pragma unroll
    for (int i = lane; i < NF_; i += 32)
        a += (double)stim_time[warp + i] * (double)stf[i];
    #pragma unroll
    for (int m = 16; m; m >>= 1) a += __shfl_xor_sync(0xffffffffu, a, m);
    if (lane == 0) d_filt[warp] = (float)a;
}

// ---------------- K2 ----------------
__global__ void k_stimdot(const float* __restrict__ spat,
                          const float* __restrict__ sf) {
    int warp = (blockIdx.x * blockDim.x + threadIdx.x) >> 5;
    int lane = threadIdx.x & 31;
    if (warp >= B_) return;
    const float* row = spat + (size_t)warp * P_;
    double a = 0.0;
    for (int p = lane; p < P_; p += 32)
        a += (double)row[p] * (double)sf[p];
    #pragma unroll
    for (int m = 16; m; m >>= 1) a += __shfl_xor_sync(0xffffffffu, a, m);
    if (lane == 0) d_stimdot[warp] = (float)a;
}

// ---------------- K-pack ----------------
__global__ void k_pack(const float* __restrict__ cc) {
    int gid  = blockIdx.x * blockDim.x + threadIdx.x;
    int warp = gid >> 5;
    int lane = gid & 31;
    int row  = warp / NW_;
    int word = warp - row * NW_;
    if (row >= B_ * NC_) return;
    int elem = word * 32 + lane;
    float v = (elem < NB_) ? cc[(size_t)row * NB_ + elem] : 0.0f;
    unsigned m = __ballot_sync(0xffffffffu, v != 0.0f);
    if (lane == 0) d_bm[row * NWP_ + word] = m;
}

// ---------------- K3: gensig (verified R5 version) ----------------
__global__ void __launch_bounds__(256)
k_gensig(const float* __restrict__ cK,
         const float* __restrict__ bias) {
    __shared__ double sKd[NC_ * 256];
    __shared__ unsigned sbm[NC_ * NWP_];

    const int tid = threadIdx.x;
    const int b   = blockIdx.y;

    for (int i = tid; i < NC_ * 256; i += 256) {
        int c = i >> 8, k = i & 255;
        sKd[i] = (k < NF_) ? (double)cK[c * NF_ + k] : 0.0;
    }
    for (int i = tid; i < NC_ * NWP_; i += 256)
        sbm[i] = d_bm[b * NC_ * NWP_ + i];
    __syncthreads();

    const int t = blockIdx.x * 256 + tid;
    if (t >= LS_) return;

    const int w0 = t >> 5;
    const int o  = t & 31;

    double a0 = 0.0, a1 = 0.0, a2 = 0.0, a3 = 0.0;
    #pragma unroll 1
    for (int c = 0; c < NC_; ++c) {
        const unsigned* bm = sbm + c * NWP_ + w0;
        const double*   kd = sKd + c * 256;
        #pragma unroll
        for (int k = 0; k < 8; k += 4) {
            unsigned w_0 = __funnelshift_r(bm[k],     bm[k + 1], o);
            unsigned w_1 = __funnelshift_r(bm[k + 1], bm[k + 2], o);
            unsigned w_2 = __funnelshift_r(bm[k + 2], bm[k + 3], o);
            unsigned w_3 = __funnelshift_r(bm[k + 3], bm[k + 4], o);
            while (w_0) { int i = __ffs(w_0) - 1; w_0 &= w_0 - 1; a0 += kd[((k    ) << 5) + i]; }
            while (w_1) { int i = __ffs(w_1) - 1; w_1 &= w_1 - 1; a1 += kd[((k + 1) << 5) + i]; }
            while (w_2) { int i = __ffs(w_2) - 1; w_2 &= w_2 - 1; a2 += kd[((k + 2) << 5) + i]; }
            while (w_3) { int i = __ffs(w_3) - 1; w_3 &= w_3 - 1; a3 += kd[((k + 3) << 5) + i]; }
        }
    }
    float coup = (float)((a0 + a1) + (a2 + a3));
    float sg = __fmul_rn(d_stimdot[b], d_filt[t]);
    sg = __fadd_rn(sg, bias[0]);
    d_gensig[b * LS_ + t] = __fadd_rn(sg, coup);
}

// ---------------- K4: simulation, R3 geometry + f32x2 seq-pair packing ----------
// 8 sequences/warp as 4 groups x (2 packed seqs). 8 lanes per group, 32 taps
// per lane, rotation mod 32, 32-step outer blocks (phase-consistent).
// Each f32x2 half executes the exact R3 scalar chain: two 16-deep FMA chains
// A,B; acc=(A+B); shfl_xor 1,2,4 reduce per half. Bitwise identical per seq.
__global__ void __launch_bounds__(128, 3)
k_sim(const float* __restrict__ init,
      const float* __restrict__ ff,
      const float* __restrict__ u,
      float* __restrict__ out) {
    const unsigned FULL = 0xffffffffu;
    const int lane = threadIdx.x & 31;
    const int gw   = (blockIdx.x * blockDim.x + threadIdx.x) >> 5;  // 0..2047
    const int b    = gw >> 4;          // 16 warps per b
    const int rq   = gw & 15;          // 8-seq group within b
    const int g    = lane >> 3;        // 0..3: seq-pair within warp
    const int q    = lane & 7;         // lane within the 8-lane group
    const int seq0 = b * R_ + rq * 8 + g * 2;   // even

    ull f2[32], w2[32];
    #pragma unroll
    for (int i = 0; i < 32; ++i) {
        int k = q * 32 + i;
        bool valid = (k < NF_);
        float fv = valid ? ff[k] : 0.0f;
        float wv = valid ? init[b * NF_ + k] : 0.0f;
        f2[i] = pk(fv, fv);
        w2[i] = pk(wv, wv);          // both seqs share the initial window
    }

    float* orow0 = out + (size_t)seq0 * NB_;
    float* orow1 = orow0 + NB_;
    for (int k = q; k < NF_; k += 8) {
        float v = init[b * NF_ + k];
        orow0[k] = v;
        orow1[k] = v;
    }

    const float* gens = d_gensig + b * LS_;
    const int src_base  = lane & 24;
    const int src_shift = src_base | ((q + 1) & 7);

    for (int t0 = 0; t0 < LS_; t0 += 32) {
        float gval = (t0 + lane < LS_) ? gens[t0 + lane] : 0.0f;
        float u0[4], u1[4];
        #pragma unroll
        for (int m = 0; m < 4; ++m) {
            int t = t0 + 8 * m + q;
            if (t < LS_) {
                ull v = *(const ull*)(u + (size_t)t * (B_ * R_) + seq0);
                upk(u0[m], u1[m], v);
            } else { u0[m] = 0.0f; u1[m] = 0.0f; }
        }

        #pragma unroll
        for (int s = 0; s < 32; ++s) {
            // packed chains: each half = exact R3 scalar chain
            ull A2 = mul2(w2[(s     ) & 31], f2[0]);
            ull B2 = mul2(w2[(16 + s) & 31], f2[16]);
            #pragma unroll
            for (int i = 1; i < 16; ++i) {
                A2 = fma2(w2[(i      + s) & 31], f2[i],      A2);
                B2 = fma2(w2[(16 + i + s) & 31], f2[16 + i], B2);
            }
            ull acc2 = add2(A2, B2);
            float a0, a1;
            upk(a0, a1, acc2);
            a0 += __shfl_xor_sync(FULL, a0, 1);
            a1 += __shfl_xor_sync(FULL, a1, 1);
            a0 += __shfl_xor_sync(FULL, a0, 2);
            a1 += __shfl_xor_sync(FULL, a1, 2);
            a0 += __shfl_xor_sync(FULL, a0, 4);
            a1 += __shfl_xor_sync(FULL, a1, 4);

            float gt  = __shfl_sync(FULL, gval, s);
            float ut0 = __shfl_sync(FULL, u0[s >> 3], src_base | (s & 7));
            float ut1 = __shfl_sync(FULL, u1[s >> 3], src_base | (s & 7));

            float g0 = gt + a0;
            float g1 = gt + a1;
            float e0 = expf(-g0);
            float e1 = expf(-g1);
            float sig0 = 1.0f / (1.0f + e0);
            float sig1 = 1.0f / (1.0f + e1);
            float sp0 = (ut0 < sig0) ? 1.0f : 0.0f;
            float sp1 = (ut1 < sig1) ? 1.0f : 0.0f;

            // immediate predicated stores (lane s&7 of each group)
            int t = t0 + s;
            if (q == (s & 7) && t < LS_) {
                orow0[NF_ + t] = sp0;
                orow1[NF_ + t] = sp1;
            }

            // shift: slot s&31 (tap 32q group boundary) <- next lane's value
            float lo, hi;
            upk(lo, hi, w2[s & 31]);
            lo = __shfl_sync(FULL, lo, src_shift);
            hi = __shfl_sync(FULL, hi, src_shift);
            w2[s & 31] = pk(lo, hi);
            // insert new spikes at tap 249 (q==7, i==25) for phase s+1
            if (q == 7) w2[(s + 26) & 31] = pk(sp0, sp1);
        }
    }
}

// ---------------- launch ----------------
extern "C" void kernel_launch(void* const* d_in, const int* in_sizes, int n_in,
                              void* d_out, int out_size) {
    (void)in_sizes; (void)n_in; (void)out_size;
    const float* stim_spat = (const float*)d_in[0];
    const float* stim_time = (const float*)d_in[1];
    const float* init      = (const float*)d_in[2];
    const float* cc        = (const float*)d_in[3];
    const float* sf        = (const float*)d_in[4];
    const float* bias      = (const float*)d_in[5];
    const float* stf       = (const float*)d_in[6];
    const float* ff        = (const float*)d_in[7];
    const float* cK        = (const float*)d_in[8];
    const float* u         = (const float*)d_in[9];
    float* out = (float*)d_out;

    int pack_threads = B_ * NC_ * NW_ * 32;
    k_pack<<<(pack_threads + 255) / 256, 256>>>(cc);

    k_filt<<<(FT_ * 32 + 255) / 256, 256>>>(stim_time, stf);
    k_stimdot<<<(B_ * 32 + 255) / 256, 256>>>(stim_spat, sf);

    dim3 g3((LS_ + 255) / 256, B_);
    k_gensig<<<g3, 256>>>(cK, bias);

    // 2048 warps (8 packed sequences each) -> 512 blocks of 128 threads
    k_sim<<<512, 128>>>(init, ff, u, out);
}